// round 13
// baseline (speedup 1.0000x reference)
#include <cuda_runtime.h>
#include <cuda_fp16.h>
#include <cstdint>
#include <math.h>

#define BB 32
#define LK 4096
#define HH 512

// ---------------- scratch (device globals; no allocations allowed) ----------
__device__ float g_qc[BB * HH];           // Wa q + Wa_b + Ua_b
__device__ float g_spart[4 * BB * LK];    // per-nchunk partial scores
__device__ float g_part[8 * BB * HH];     // context partials per 512-l chunk
__device__ float g_wbuf[BB * LK];         // fallback weights output
__device__ float g_cbuf[BB * HH];         // fallback context output
__device__ __half g_Ub16[4 * 16 * 128 * 32];   // Ua_w fp16 granules [z][kt][row][c][8]
__device__ __half g_keys16[(size_t)BB * LK * HH];  // keys fp16 (live tiles only)

// ================= helpers ===================================================
__device__ __forceinline__ uint32_t smem_u32(const void* p) {
    uint32_t a;
    asm("{ .reg .u64 t; cvta.to.shared.u64 t, %1; cvt.u32.u64 %0, t; }"
        : "=r"(a) : "l"(p));
    return a;
}
__device__ __forceinline__ float fast_tanh(float x) {
    float cx = fminf(fmaxf(x, -15.f), 15.f);
    float e; asm("ex2.approx.f32 %0, %1;" : "=f"(e) : "f"(cx * 2.885390082f));
    float r; asm("rcp.approx.f32 %0, %1;" : "=f"(r) : "f"(e + 1.f));
    return (e - 1.f) * r;
}
__device__ __forceinline__ void cpa16(uint32_t saddr, const void* g) {
    asm volatile("cp.async.cg.shared.global [%0], [%1], 16;" :: "r"(saddr), "l"(g));
}
#define CP_COMMIT() asm volatile("cp.async.commit_group;" ::: "memory")
#define CP_WAIT2()  asm volatile("cp.async.wait_group 2;" ::: "memory")

#define LDSM_X4(r0, r1, r2, r3, addr)                                         \
    asm volatile("ldmatrix.sync.aligned.m8n8.x4.shared.b16 {%0,%1,%2,%3}, [%4];" \
        : "=r"(r0), "=r"(r1), "=r"(r2), "=r"(r3) : "r"(addr))

#define MMA_F16(d, a, b)                                                      \
    asm volatile(                                                             \
        "mma.sync.aligned.m16n8k16.row.col.f32.f16.f16.f32 "                  \
        "{%0,%1,%2,%3}, {%4,%5,%6,%7}, {%8,%9}, {%0,%1,%2,%3};"               \
        : "+f"((d)[0]), "+f"((d)[1]), "+f"((d)[2]), "+f"((d)[3])              \
        : "r"((a)[0]), "r"((a)[1]), "r"((a)[2]), "r"((a)[3]),                 \
          "r"((b)[0]), "r"((b)[1]))

__device__ __forceinline__ uint32_t pack2(float x, float y) {
    __half2 h = __floats2half2_rn(x, y);
    return *(uint32_t*)&h;
}

// ---------------- 0) merged prep: convK | convB | qc -------------------------
// blocks [0,1024): convK tile (b=bx>>5, chunk=bx&31)
// blocks [1024,1088): convB (gid = (bx-1024)*512+tid)
// blocks [1088,1120): qc (b = bx-1088)
__global__ __launch_bounds__(512) void k_prep(
    const float* __restrict__ keys, const float* __restrict__ Ua_w,
    const float* __restrict__ query, const float* __restrict__ Wa_w,
    const float* __restrict__ Wa_b, const float* __restrict__ Ua_b,
    const int* __restrict__ valid) {
    __shared__ float qs[HH];
    int bx = blockIdx.x, tid = threadIdx.x;
    if (bx < 1024) {
        int b = bx >> 5, chunk = bx & 31;
        if (chunk * 128 >= valid[b]) return;
        size_t base = ((size_t)b * LK + chunk * 128) * HH;
        const float* src = keys + base;
        __half* dst = g_keys16 + base;
        #pragma unroll
        for (int it = 0; it < 16; it++) {
            int off = (it * 512 + tid) * 8;
            float4 v0 = *(const float4*)(src + off);
            float4 v1 = *(const float4*)(src + off + 4);
            uint4 o = make_uint4(pack2(v0.x, v0.y), pack2(v0.z, v0.w),
                                 pack2(v1.x, v1.y), pack2(v1.z, v1.w));
            *(uint4*)(dst + off) = o;
        }
    } else if (bx < 1088) {
        int gid = (bx - 1024) * 512 + tid;   // 32768 granules
        int c = gid & 3;
        int t = gid >> 2;
        int row = t & 127;
        int kt = (t >> 7) & 15;
        int z = t >> 11;
        const float* src = Ua_w + ((size_t)(z * 128 + row) * HH + kt * 32 + c * 8);
        __half* dst = g_Ub16 + ((size_t)gid * 8);
        #pragma unroll
        for (int j = 0; j < 8; j++) dst[j] = __float2half_rn(src[j]);
    } else {
        int b = bx - 1088, h = tid;
        qs[h] = query[b * HH + h];
        __syncthreads();
        float acc = 0.f;
        const float* wr = Wa_w + (size_t)h * HH;
        #pragma unroll 8
        for (int j = 0; j < HH; j++) acc += qs[j] * wr[j];
        g_qc[b * HH + h] = acc + Wa_b[h] + Ua_b[h];
    }
}

// ---------------- 1) fp16 mma GEMM, all-cp.async, static grid ----------------
// CTA: 128 l x 128 n. bx: lt=bx>>2, z=bx&3 (z fastest -> A shared via L2).
#define STG 10240                  // bytes per stage (128 rows * 80)
#define AOFF (4 * STG)             // A stages at 40960 + s*STG
#define QCOFF 81920
#define VAOFF 82432
#define REDOFF 82944
#define SMEM_SCORE 84992
__global__ __launch_bounds__(256, 2) void k_score_mma(
    const float* __restrict__ Va_w, const int* __restrict__ valid) {
    extern __shared__ char smem[];
    int lt = blockIdx.x >> 2, z = blockIdx.x & 3;
    int b = blockIdx.y;
    int l0 = lt * 128;
    int v = valid[b];
    if (l0 >= v) return;

    int tid = threadIdx.x;
    int wid = tid >> 5, lane = tid & 31;
    int mw = wid & 3, nw = wid >> 2;       // warp grid 4(M) x 2(N)
    int g = lane >> 2, tig = lane & 3;
    int n0 = z * 128;
    uint32_t sb = smem_u32(smem);

    float* qc_s = (float*)(smem + QCOFF);
    float* va_s = (float*)(smem + VAOFF);
    float* red  = (float*)(smem + REDOFF);
    if (tid < 128) {
        qc_s[tid] = g_qc[b * HH + n0 + tid];
        va_s[tid] = Va_w[n0 + tid];
    }
    __syncthreads();

    // ---- producer addressing (pure cp.async) ----
    int prow = tid >> 1, pseg = tid & 1;   // 2 threads per row, 32B each
    const __half* gA = g_keys16 + ((size_t)b * LK + l0 + prow) * HH + pseg * 16;
    uint32_t aDst0 = sb + AOFF + prow * 80 + pseg * 32;
    const __half* gB = g_Ub16 + (size_t)z * (16 * 128 * 32)
                     + ((size_t)prow * 4 + pseg * 2) * 8;
    uint32_t bDst0 = sb + prow * 80 + pseg * 32;

    // ---- ldmatrix addressing ----
    uint32_t aRow[2], bRow[4];
    #pragma unroll
    for (int mi = 0; mi < 2; mi++)
        aRow[mi] = (uint32_t)((mw * 32 + mi * 16 + ((lane >> 3) & 1) * 8 + (lane & 7)) * 80);
    #pragma unroll
    for (int nb4 = 0; nb4 < 4; nb4++)
        bRow[nb4] = (uint32_t)((nw * 64 + (nb4 * 2 + (lane >> 4)) * 8 + (lane & 7)) * 80);
    uint32_t cAh = (uint32_t)(lane >> 4) << 4;
    uint32_t cBh = (uint32_t)((lane >> 3) & 1) << 4;

    float d[2][8][4];
    #pragma unroll
    for (int mi = 0; mi < 2; mi++)
        #pragma unroll
        for (int ni = 0; ni < 8; ni++)
            #pragma unroll
            for (int jj = 0; jj < 4; jj++) d[mi][ni][jj] = 0.f;

    // ---- prologue: stages 0..2 for A and B ----
    #pragma unroll
    for (int s = 0; s < 3; s++) {
        const __half* sa = gA + s * 32;
        cpa16(aDst0 + s * STG, sa);
        cpa16(aDst0 + s * STG + 16, sa + 8);
        const __half* sbp = gB + (size_t)s * (128 * 32);
        cpa16(bDst0 + s * STG, sbp);
        cpa16(bDst0 + s * STG + 16, sbp + 8);
        CP_COMMIT();
    }

    for (int kt = 0; kt < 16; kt++) {
        CP_WAIT2();
        __syncthreads();
        if (kt + 3 < 16) {
            int s = kt + 3;
            const __half* sa = gA + s * 32;
            uint32_t ad = aDst0 + (s & 3) * STG;
            cpa16(ad, sa);
            cpa16(ad + 16, sa + 8);
            const __half* sbp = gB + (size_t)s * (128 * 32);
            uint32_t bd = bDst0 + (s & 3) * STG;
            cpa16(bd, sbp);
            cpa16(bd + 16, sbp + 8);
        }
        CP_COMMIT();

        uint32_t aBase = sb + AOFF + (kt & 3) * STG;
        uint32_t bBase = sb + (kt & 3) * STG;
        #pragma unroll
        for (int kg = 0; kg < 2; kg++) {
            uint32_t cA = ((uint32_t)(kg * 2) << 4) + cAh;
            uint32_t cB = ((uint32_t)(kg * 2) << 4) + cBh;
            uint32_t a[2][4], bf[8][2];
            #pragma unroll
            for (int mi = 0; mi < 2; mi++)
                LDSM_X4(a[mi][0], a[mi][1], a[mi][2], a[mi][3],
                        aBase + aRow[mi] + cA);
            // first half of B, then 8 MMAs (second B pair overlaps MMA burst)
            LDSM_X4(bf[0][0], bf[0][1], bf[1][0], bf[1][1], bBase + bRow[0] + cB);
            LDSM_X4(bf[2][0], bf[2][1], bf[3][0], bf[3][1], bBase + bRow[1] + cB);
            #pragma unroll
            for (int mi = 0; mi < 2; mi++)
                #pragma unroll
                for (int ni = 0; ni < 4; ni++)
                    MMA_F16(d[mi][ni], a[mi], bf[ni]);
            LDSM_X4(bf[4][0], bf[4][1], bf[5][0], bf[5][1], bBase + bRow[2] + cB);
            LDSM_X4(bf[6][0], bf[6][1], bf[7][0], bf[7][1], bBase + bRow[3] + cB);
            #pragma unroll
            for (int mi = 0; mi < 2; mi++)
                #pragma unroll
                for (int ni = 4; ni < 8; ni++)
                    MMA_F16(d[mi][ni], a[mi], bf[ni]);
        }
    }

    // ---- epilogue: tanh + Va dot, reduce across n ---------------------------
    float rs[2][2] = {{0.f, 0.f}, {0.f, 0.f}};
    #pragma unroll
    for (int mi = 0; mi < 2; mi++)
        #pragma unroll
        for (int ni = 0; ni < 8; ni++)
            #pragma unroll
            for (int jj = 0; jj < 4; jj++) {
                int nl = nw * 64 + ni * 8 + tig * 2 + (jj & 1);
                rs[mi][jj >> 1] += fast_tanh(d[mi][ni][jj] + qc_s[nl]) * va_s[nl];
            }
    #pragma unroll
    for (int mi = 0; mi < 2; mi++)
        #pragma unroll
        for (int hh = 0; hh < 2; hh++) {
            float s = rs[mi][hh];
            s += __shfl_xor_sync(0xffffffffu, s, 1);
            s += __shfl_xor_sync(0xffffffffu, s, 2);
            rs[mi][hh] = s;
        }
    if (tig == 0) {
        #pragma unroll
        for (int mi = 0; mi < 2; mi++)
            #pragma unroll
            for (int hh = 0; hh < 2; hh++) {
                int row = mw * 32 + mi * 16 + hh * 8 + g;
                red[row * 2 + nw] = rs[mi][hh];
            }
    }
    __syncthreads();
    if (tid < 128)
        g_spart[((size_t)z * BB + b) * LK + l0 + tid] = red[tid * 2] + red[tid * 2 + 1];
}

// ---------------- 2) fused softmax + context chunk ---------------------------
// grid (8, BB), 256 thr. Each CTA: full softmax of batch b (redundant, cheap),
// writes weights for its 512-l chunk, accumulates ctx partial for the chunk.
__global__ __launch_bounds__(256) void k_wctx(
    const float* __restrict__ Va_b, const float* __restrict__ temp,
    const int* __restrict__ valid, float* __restrict__ w_out) {
    __shared__ float se[LK];
    __shared__ float rbuf[256];
    int chunk = blockIdx.x, b = blockIdx.y;
    int tid = threadIdx.x;
    int v = valid[b];
    int lbase = chunk * 512;
    float* dst = g_part + ((size_t)chunk * BB + b) * HH;

    if (lbase >= v) {                     // dead chunk: exact zeros
        for (int l = tid; l < 512; l += 256)
            w_out[(size_t)b * LK + lbase + l] = 0.f;
        dst[tid * 2] = 0.f;
        dst[tid * 2 + 1] = 0.f;
        return;
    }

    float vb = Va_b[0], invT = 1.f / temp[0];
    const float* p0 = g_spart + ((size_t)0 * BB + b) * LK;
    const float* p1 = g_spart + ((size_t)1 * BB + b) * LK;
    const float* p2 = g_spart + ((size_t)2 * BB + b) * LK;
    const float* p3 = g_spart + ((size_t)3 * BB + b) * LK;
    float mx = -1e30f;
    for (int l = tid; l < LK; l += 256) {
        float s = (l < v) ? (p0[l] + p1[l] + p2[l] + p3[l] + vb) * invT : -1e9f;
        se[l] = s; mx = fmaxf(mx, s);
    }
    rbuf[tid] = mx; __syncthreads();
    for (int s = 128; s > 0; s >>= 1) {
        if (tid < s) rbuf[tid] = fmaxf(rbuf[tid], rbuf[tid + s]);
        __syncthreads();
    }
    mx = rbuf[0]; __syncthreads();
    float sum = 0.f;
    for (int l = tid; l < LK; l += 256) { float e = expf(se[l] - mx); se[l] = e; sum += e; }
    rbuf[tid] = sum; __syncthreads();
    for (int s = 128; s > 0; s >>= 1) {
        if (tid < s) rbuf[tid] += rbuf[tid + s];
        __syncthreads();
    }
    float inv = 1.f / rbuf[0];
    // se now stable (sum-reduction barriers); weights = se * inv
    for (int l = tid; l < 512; l += 256)
        w_out[(size_t)b * LK + lbase + l] = se[lbase + l] * inv;

    // ---- context over this chunk (unnormalized, scale at end) ----
    int lend = min(512, v - lbase);
    const __half2* kb =
        (const __half2*)(g_keys16 + ((size_t)b * LK + lbase) * HH) + tid;
    const int str = HH / 2;
    const float* wse = se + lbase;
    float ax0 = 0.f, ay0 = 0.f, ax1 = 0.f, ay1 = 0.f;
    int l = 0;
    for (; l + 2 <= lend; l += 2) {
        float2 k0 = __half22float2(kb[(size_t)l * str]);
        float2 k1 = __half22float2(kb[(size_t)(l + 1) * str]);
        float w0 = wse[l], w1 = wse[l + 1];
        ax0 += w0 * k0.x; ay0 += w0 * k0.y;
        ax1 += w1 * k1.x; ay1 += w1 * k1.y;
    }
    if (l < lend) {
        float2 k0 = __half22float2(kb[(size_t)l * str]);
        float w0 = wse[l];
        ax0 += w0 * k0.x; ay0 += w0 * k0.y;
    }
    dst[tid * 2]     = (ax0 + ax1) * inv;
    dst[tid * 2 + 1] = (ay0 + ay1) * inv;
}

// ---------------- 3) reduce partials -> context ------------------------------
__global__ void k_ctxred(float* __restrict__ ctx_out) {
    int b = blockIdx.x, h = threadIdx.x;
    float s = 0.f;
    #pragma unroll
    for (int c = 0; c < 8; c++) s += g_part[((size_t)c * BB + b) * HH + h];
    ctx_out[b * HH + h] = s;
}

// ---------------- launch ------------------------------------------------------
extern "C" void kernel_launch(void* const* d_in, const int* in_sizes, int n_in,
                              void* d_out, int out_size) {
    const float* query = (const float*)d_in[0];
    const float* keys  = (const float*)d_in[1];
    const float* Wa_w  = (const float*)d_in[2];
    const float* Wa_b  = (const float*)d_in[3];
    const float* Ua_w  = (const float*)d_in[4];
    const float* Ua_b  = (const float*)d_in[5];
    const float* Va_w  = (const float*)d_in[6];
    const float* Va_b  = (const float*)d_in[7];
    const float* temp  = (const float*)d_in[8];
    const int*   valid = (const int*)d_in[9];

    float* out = (float*)d_out;
    float* ctx_out;
    float* w_out;
    void *cb = nullptr, *wb = nullptr;
    cudaGetSymbolAddress(&cb, g_cbuf);
    cudaGetSymbolAddress(&wb, g_wbuf);
    if (out_size >= BB * HH + BB * LK) { ctx_out = out; w_out = out + BB * HH; }
    else if (out_size == BB * LK)      { w_out = out; ctx_out = (float*)cb; }
    else                               { ctx_out = out; w_out = (float*)wb; }

    cudaFuncSetAttribute(k_score_mma, cudaFuncAttributeMaxDynamicSharedMemorySize,
                         SMEM_SCORE);

    k_prep<<<1120, 512>>>(keys, Ua_w, query, Wa_w, Wa_b, Ua_b, valid);
    k_score_mma<<<dim3(4 * (LK / 128), BB), 256, SMEM_SCORE>>>(Va_w, valid);
    k_wctx<<<dim3(8, BB), 256>>>(Va_b, temp, valid, w_out);
    k_ctxred<<<BB, HH>>>(ctx_out);
}

// round 14
// speedup vs baseline: 1.1197x; 1.1197x over previous
#include <cuda_runtime.h>
#include <cuda_fp16.h>
#include <cstdint>
#include <math.h>

#define BB 32
#define LK 4096
#define HH 512

// ---------------- scratch (device globals; no allocations allowed) ----------
__device__ float g_qc[BB * HH];           // Wa q + Wa_b + Ua_b
__device__ float g_spart[4 * BB * LK];    // per-nchunk partial scores
__device__ float g_part[32 * BB * HH];    // context partials per 128-l chunk
__device__ float g_wbuf[BB * LK];         // fallback weights output
__device__ float g_cbuf[BB * HH];         // fallback context output
__device__ __half g_Ub16[4 * 16 * 128 * 32];   // Ua_w fp16 granules [z][kt][row][c][8]
__device__ __half g_keys16[(size_t)BB * LK * HH];  // keys fp16 (live tiles only)

// ================= helpers ===================================================
__device__ __forceinline__ uint32_t smem_u32(const void* p) {
    uint32_t a;
    asm("{ .reg .u64 t; cvta.to.shared.u64 t, %1; cvt.u32.u64 %0, t; }"
        : "=r"(a) : "l"(p));
    return a;
}
__device__ __forceinline__ float fast_tanh(float x) {
    float cx = fminf(fmaxf(x, -15.f), 15.f);
    float e; asm("ex2.approx.f32 %0, %1;" : "=f"(e) : "f"(cx * 2.885390082f));
    float r; asm("rcp.approx.f32 %0, %1;" : "=f"(r) : "f"(e + 1.f));
    return (e - 1.f) * r;
}
__device__ __forceinline__ void cpa16(uint32_t saddr, const void* g) {
    asm volatile("cp.async.cg.shared.global [%0], [%1], 16;" :: "r"(saddr), "l"(g));
}
#define CP_COMMIT() asm volatile("cp.async.commit_group;" ::: "memory")
#define CP_WAIT2()  asm volatile("cp.async.wait_group 2;" ::: "memory")

#define LDSM_X4(r0, r1, r2, r3, addr)                                         \
    asm volatile("ldmatrix.sync.aligned.m8n8.x4.shared.b16 {%0,%1,%2,%3}, [%4];" \
        : "=r"(r0), "=r"(r1), "=r"(r2), "=r"(r3) : "r"(addr))

#define MMA_F16(d, a, b)                                                      \
    asm volatile(                                                             \
        "mma.sync.aligned.m16n8k16.row.col.f32.f16.f16.f32 "                  \
        "{%0,%1,%2,%3}, {%4,%5,%6,%7}, {%8,%9}, {%0,%1,%2,%3};"               \
        : "+f"((d)[0]), "+f"((d)[1]), "+f"((d)[2]), "+f"((d)[3])              \
        : "r"((a)[0]), "r"((a)[1]), "r"((a)[2]), "r"((a)[3]),                 \
          "r"((b)[0]), "r"((b)[1]))

__device__ __forceinline__ uint32_t pack2(float x, float y) {
    __half2 h = __floats2half2_rn(x, y);
    return *(uint32_t*)&h;
}

// ---------------- 0) merged prep: convK | convB | qc -------------------------
// blocks [0,1024): convK tile (b=bx>>5, chunk=bx&31)
// blocks [1024,1088): convB (gid = (bx-1024)*512+tid)
// blocks [1088,1120): qc (b = bx-1088)
__global__ __launch_bounds__(512) void k_prep(
    const float* __restrict__ keys, const float* __restrict__ Ua_w,
    const float* __restrict__ query, const float* __restrict__ Wa_w,
    const float* __restrict__ Wa_b, const float* __restrict__ Ua_b,
    const int* __restrict__ valid) {
    __shared__ float qs[HH];
    int bx = blockIdx.x, tid = threadIdx.x;
    if (bx < 1024) {
        int b = bx >> 5, chunk = bx & 31;
        if (chunk * 128 >= valid[b]) return;
        size_t base = ((size_t)b * LK + chunk * 128) * HH;
        const float* src = keys + base;
        __half* dst = g_keys16 + base;
        #pragma unroll
        for (int it = 0; it < 16; it++) {
            int off = (it * 512 + tid) * 8;
            float4 v0 = *(const float4*)(src + off);
            float4 v1 = *(const float4*)(src + off + 4);
            uint4 o = make_uint4(pack2(v0.x, v0.y), pack2(v0.z, v0.w),
                                 pack2(v1.x, v1.y), pack2(v1.z, v1.w));
            *(uint4*)(dst + off) = o;
        }
    } else if (bx < 1088) {
        int gid = (bx - 1024) * 512 + tid;   // 32768 granules
        int c = gid & 3;
        int t = gid >> 2;
        int row = t & 127;
        int kt = (t >> 7) & 15;
        int z = t >> 11;
        const float* src = Ua_w + ((size_t)(z * 128 + row) * HH + kt * 32 + c * 8);
        __half* dst = g_Ub16 + ((size_t)gid * 8);
        #pragma unroll
        for (int j = 0; j < 8; j++) dst[j] = __float2half_rn(src[j]);
    } else {
        int b = bx - 1088, h = tid;
        qs[h] = query[b * HH + h];
        __syncthreads();
        float acc = 0.f;
        const float* wr = Wa_w + (size_t)h * HH;
        #pragma unroll 8
        for (int j = 0; j < HH; j++) acc += qs[j] * wr[j];
        g_qc[b * HH + h] = acc + Wa_b[h] + Ua_b[h];
    }
}

// ---------------- 1) fp16 mma GEMM, all-cp.async (round-11 proven body) ------
#define STG 10240                  // bytes per stage (128 rows * 80)
#define AOFF (4 * STG)             // A stages at 40960 + s*STG
#define QCOFF 81920
#define VAOFF 82432
#define REDOFF 82944
#define SMEM_SCORE 84992
__global__ __launch_bounds__(256, 2) void k_score_mma(
    const float* __restrict__ Va_w, const int* __restrict__ valid) {
    extern __shared__ char smem[];
    int lt = blockIdx.x >> 2, z = blockIdx.x & 3;
    int b = blockIdx.y;
    int l0 = lt * 128;
    int v = valid[b];
    if (l0 >= v) return;

    int tid = threadIdx.x;
    int wid = tid >> 5, lane = tid & 31;
    int mw = wid & 3, nw = wid >> 2;       // warp grid 4(M) x 2(N)
    int g = lane >> 2, tig = lane & 3;
    int n0 = z * 128;
    uint32_t sb = smem_u32(smem);

    float* qc_s = (float*)(smem + QCOFF);
    float* va_s = (float*)(smem + VAOFF);
    float* red  = (float*)(smem + REDOFF);
    if (tid < 128) {
        qc_s[tid] = g_qc[b * HH + n0 + tid];
        va_s[tid] = Va_w[n0 + tid];
    }
    __syncthreads();

    // ---- producer addressing (pure cp.async) ----
    int prow = tid >> 1, pseg = tid & 1;   // 2 threads per row, 32B each
    const __half* gA = g_keys16 + ((size_t)b * LK + l0 + prow) * HH + pseg * 16;
    uint32_t aDst0 = sb + AOFF + prow * 80 + pseg * 32;
    const __half* gB = g_Ub16 + (size_t)z * (16 * 128 * 32)
                     + ((size_t)prow * 4 + pseg * 2) * 8;
    uint32_t bDst0 = sb + prow * 80 + pseg * 32;

    // ---- ldmatrix addressing ----
    uint32_t aRow[2], bRow[4];
    #pragma unroll
    for (int mi = 0; mi < 2; mi++)
        aRow[mi] = (uint32_t)((mw * 32 + mi * 16 + ((lane >> 3) & 1) * 8 + (lane & 7)) * 80);
    #pragma unroll
    for (int nb4 = 0; nb4 < 4; nb4++)
        bRow[nb4] = (uint32_t)((nw * 64 + (nb4 * 2 + (lane >> 4)) * 8 + (lane & 7)) * 80);
    uint32_t cAh = (uint32_t)(lane >> 4) << 4;
    uint32_t cBh = (uint32_t)((lane >> 3) & 1) << 4;

    float d[2][8][4];
    #pragma unroll
    for (int mi = 0; mi < 2; mi++)
        #pragma unroll
        for (int ni = 0; ni < 8; ni++)
            #pragma unroll
            for (int jj = 0; jj < 4; jj++) d[mi][ni][jj] = 0.f;

    // ---- prologue: stages 0..2 for A and B ----
    #pragma unroll
    for (int s = 0; s < 3; s++) {
        const __half* sa = gA + s * 32;
        cpa16(aDst0 + s * STG, sa);
        cpa16(aDst0 + s * STG + 16, sa + 8);
        const __half* sbp = gB + (size_t)s * (128 * 32);
        cpa16(bDst0 + s * STG, sbp);
        cpa16(bDst0 + s * STG + 16, sbp + 8);
        CP_COMMIT();
    }

    for (int kt = 0; kt < 16; kt++) {
        CP_WAIT2();
        __syncthreads();
        if (kt + 3 < 16) {
            int s = kt + 3;
            const __half* sa = gA + s * 32;
            uint32_t ad = aDst0 + (s & 3) * STG;
            cpa16(ad, sa);
            cpa16(ad + 16, sa + 8);
            const __half* sbp = gB + (size_t)s * (128 * 32);
            uint32_t bd = bDst0 + (s & 3) * STG;
            cpa16(bd, sbp);
            cpa16(bd + 16, sbp + 8);
        }
        CP_COMMIT();

        uint32_t aBase = sb + AOFF + (kt & 3) * STG;
        uint32_t bBase = sb + (kt & 3) * STG;
        #pragma unroll
        for (int kg = 0; kg < 2; kg++) {
            uint32_t cA = ((uint32_t)(kg * 2) << 4) + cAh;
            uint32_t cB = ((uint32_t)(kg * 2) << 4) + cBh;
            uint32_t a[2][4], bf[8][2];
            #pragma unroll
            for (int mi = 0; mi < 2; mi++)
                LDSM_X4(a[mi][0], a[mi][1], a[mi][2], a[mi][3],
                        aBase + aRow[mi] + cA);
            #pragma unroll
            for (int nb4 = 0; nb4 < 4; nb4++)
                LDSM_X4(bf[nb4 * 2][0], bf[nb4 * 2][1],
                        bf[nb4 * 2 + 1][0], bf[nb4 * 2 + 1][1],
                        bBase + bRow[nb4] + cB);
            #pragma unroll
            for (int mi = 0; mi < 2; mi++)
                #pragma unroll
                for (int ni = 0; ni < 8; ni++)
                    MMA_F16(d[mi][ni], a[mi], bf[ni]);
        }
    }

    // ---- epilogue: tanh + Va dot, reduce across n ---------------------------
    float rs[2][2] = {{0.f, 0.f}, {0.f, 0.f}};
    #pragma unroll
    for (int mi = 0; mi < 2; mi++)
        #pragma unroll
        for (int ni = 0; ni < 8; ni++)
            #pragma unroll
            for (int jj = 0; jj < 4; jj++) {
                int nl = nw * 64 + ni * 8 + tig * 2 + (jj & 1);
                rs[mi][jj >> 1] += fast_tanh(d[mi][ni][jj] + qc_s[nl]) * va_s[nl];
            }
    #pragma unroll
    for (int mi = 0; mi < 2; mi++)
        #pragma unroll
        for (int hh = 0; hh < 2; hh++) {
            float s = rs[mi][hh];
            s += __shfl_xor_sync(0xffffffffu, s, 1);
            s += __shfl_xor_sync(0xffffffffu, s, 2);
            rs[mi][hh] = s;
        }
    if (tig == 0) {
        #pragma unroll
        for (int mi = 0; mi < 2; mi++)
            #pragma unroll
            for (int hh = 0; hh < 2; hh++) {
                int row = mw * 32 + mi * 16 + hh * 8 + g;
                red[row * 2 + nw] = rs[mi][hh];
            }
    }
    __syncthreads();
    if (tid < 128)
        g_spart[((size_t)z * BB + b) * LK + l0 + tid] = red[tid * 2] + red[tid * 2 + 1];
}

// ---------------- 2) softmax over Lk per batch (sums 4 partials) -------------
__global__ void k_softmax(const float* __restrict__ Va_b, const float* __restrict__ temp,
                          const int* __restrict__ valid, float* __restrict__ w_out) {
    __shared__ float se[LK];
    __shared__ float rbuf[1024];
    int b = blockIdx.x, tid = threadIdx.x;
    int v = valid[b];
    float vb = Va_b[0], invT = 1.f / temp[0];
    const float* p0 = g_spart + ((size_t)0 * BB + b) * LK;
    const float* p1 = g_spart + ((size_t)1 * BB + b) * LK;
    const float* p2 = g_spart + ((size_t)2 * BB + b) * LK;
    const float* p3 = g_spart + ((size_t)3 * BB + b) * LK;
    float mx = -1e30f;
    for (int l = tid; l < LK; l += 1024) {
        float s = (l < v) ? (p0[l] + p1[l] + p2[l] + p3[l] + vb) * invT : -1e9f;
        se[l] = s; mx = fmaxf(mx, s);
    }
    rbuf[tid] = mx; __syncthreads();
    for (int s = 512; s > 0; s >>= 1) {
        if (tid < s) rbuf[tid] = fmaxf(rbuf[tid], rbuf[tid + s]);
        __syncthreads();
    }
    mx = rbuf[0]; __syncthreads();
    float sum = 0.f;
    for (int l = tid; l < LK; l += 1024) { float e = expf(se[l] - mx); se[l] = e; sum += e; }
    rbuf[tid] = sum; __syncthreads();
    for (int s = 512; s > 0; s >>= 1) {
        if (tid < s) rbuf[tid] += rbuf[tid + s];
        __syncthreads();
    }
    float inv = 1.f / rbuf[0];
    for (int l = tid; l < LK; l += 1024) w_out[(size_t)b * LK + l] = se[l] * inv;
}

// ---------------- 3) context partials (half2-vectorized, coalesced) ----------
__global__ __launch_bounds__(256) void k_ctx(const float* __restrict__ w,
                                             const int* __restrict__ valid) {
    __shared__ float ws[128];
    int b = blockIdx.y;
    int chunk = blockIdx.x;
    int lbase = chunk * 128;
    int tid = threadIdx.x;               // 0..255 -> h pair (2*tid, 2*tid+1)
    int v = valid[b];
    float ax0 = 0.f, ay0 = 0.f, ax1 = 0.f, ay1 = 0.f;
    if (lbase < v) {
        int lend = min(128, v - lbase);
        if (tid < 128) ws[tid] = w[(size_t)b * LK + lbase + tid];
        __syncthreads();
        const __half2* kb =
            (const __half2*)(g_keys16 + ((size_t)b * LK + lbase) * HH) + tid;
        const int str = HH / 2;          // half2 stride per row
        int l = 0;
        for (; l + 2 <= lend; l += 2) {
            float2 k0 = __half22float2(kb[(size_t)l * str]);
            float2 k1 = __half22float2(kb[(size_t)(l + 1) * str]);
            float w0 = ws[l], w1 = ws[l + 1];
            ax0 += w0 * k0.x; ay0 += w0 * k0.y;
            ax1 += w1 * k1.x; ay1 += w1 * k1.y;
        }
        if (l < lend) {
            float2 k0 = __half22float2(kb[(size_t)l * str]);
            float w0 = ws[l];
            ax0 += w0 * k0.x; ay0 += w0 * k0.y;
        }
    }
    float* dst = g_part + ((size_t)chunk * BB + b) * HH;
    dst[tid * 2]     = ax0 + ax1;
    dst[tid * 2 + 1] = ay0 + ay1;
}

// ---------------- 4) reduce partials -> context ------------------------------
__global__ void k_ctxred(float* __restrict__ ctx_out) {
    int b = blockIdx.x, h = threadIdx.x;
    float s = 0.f;
    #pragma unroll
    for (int c = 0; c < 32; c++) s += g_part[((size_t)c * BB + b) * HH + h];
    ctx_out[b * HH + h] = s;
}

// ---------------- launch ------------------------------------------------------
extern "C" void kernel_launch(void* const* d_in, const int* in_sizes, int n_in,
                              void* d_out, int out_size) {
    const float* query = (const float*)d_in[0];
    const float* keys  = (const float*)d_in[1];
    const float* Wa_w  = (const float*)d_in[2];
    const float* Wa_b  = (const float*)d_in[3];
    const float* Ua_w  = (const float*)d_in[4];
    const float* Ua_b  = (const float*)d_in[5];
    const float* Va_w  = (const float*)d_in[6];
    const float* Va_b  = (const float*)d_in[7];
    const float* temp  = (const float*)d_in[8];
    const int*   valid = (const int*)d_in[9];

    float* out = (float*)d_out;
    float* ctx_out;
    float* w_out;
    void *cb = nullptr, *wb = nullptr;
    cudaGetSymbolAddress(&cb, g_cbuf);
    cudaGetSymbolAddress(&wb, g_wbuf);
    if (out_size >= BB * HH + BB * LK) { ctx_out = out; w_out = out + BB * HH; }
    else if (out_size == BB * LK)      { w_out = out; ctx_out = (float*)cb; }
    else                               { ctx_out = out; w_out = (float*)wb; }

    cudaFuncSetAttribute(k_score_mma, cudaFuncAttributeMaxDynamicSharedMemorySize,
                         SMEM_SCORE);

    k_prep<<<1120, 512>>>(keys, Ua_w, query, Wa_w, Wa_b, Ua_b, valid);
    k_score_mma<<<dim3(4 * (LK / 128), BB), 256, SMEM_SCORE>>>(Va_w, valid);
    k_softmax<<<BB, 1024>>>(Va_b, temp, valid, w_out);
    k_ctx<<<dim3(LK / 128, BB), 256>>>(w_out, valid);
    k_ctxred<<<BB, HH>>>(ctx_out);
}

// round 15
// speedup vs baseline: 1.4438x; 1.2894x over previous
#include <cuda_runtime.h>
#include <cuda_fp16.h>
#include <cstdint>
#include <math.h>

#define BB 32
#define LK 4096
#define HH 512

// ---------------- scratch (device globals; no allocations allowed) ----------
__device__ float g_qc[BB * HH];           // Wa q + Wa_b + Ua_b
__device__ float g_spart[4 * BB * LK];    // per-nchunk partial scores
__device__ float g_part[32 * BB * HH];    // context partials per 128-l chunk
__device__ float g_wbuf[BB * LK];         // fallback weights output
__device__ float g_cbuf[BB * HH];         // fallback context output
__device__ __half g_Ub16[4 * 16 * 128 * 32];   // Ua_w fp16 granules [z][kt][row][c][8]
__device__ __half g_keys16[(size_t)BB * LK * HH];  // keys fp16 (live tiles only)

// ================= helpers ===================================================
__device__ __forceinline__ uint32_t smem_u32(const void* p) {
    uint32_t a;
    asm("{ .reg .u64 t; cvta.to.shared.u64 t, %1; cvt.u32.u64 %0, t; }"
        : "=r"(a) : "l"(p));
    return a;
}
__device__ __forceinline__ float fast_tanh(float x) {
    float cx = fminf(fmaxf(x, -15.f), 15.f);
    float e; asm("ex2.approx.f32 %0, %1;" : "=f"(e) : "f"(cx * 2.885390082f));
    float r; asm("rcp.approx.f32 %0, %1;" : "=f"(r) : "f"(e + 1.f));
    return (e - 1.f) * r;
}
__device__ __forceinline__ void cpa16(uint32_t saddr, const void* g) {
    asm volatile("cp.async.cg.shared.global [%0], [%1], 16;" :: "r"(saddr), "l"(g));
}
#define CP_COMMIT() asm volatile("cp.async.commit_group;" ::: "memory")
#define CP_WAIT2()  asm volatile("cp.async.wait_group 2;" ::: "memory")

#define LDSM_X4(r0, r1, r2, r3, addr)                                         \
    asm volatile("ldmatrix.sync.aligned.m8n8.x4.shared.b16 {%0,%1,%2,%3}, [%4];" \
        : "=r"(r0), "=r"(r1), "=r"(r2), "=r"(r3) : "r"(addr))

#define MMA_F16(d, a, b)                                                      \
    asm volatile(                                                             \
        "mma.sync.aligned.m16n8k16.row.col.f32.f16.f16.f32 "                  \
        "{%0,%1,%2,%3}, {%4,%5,%6,%7}, {%8,%9}, {%0,%1,%2,%3};"               \
        : "+f"((d)[0]), "+f"((d)[1]), "+f"((d)[2]), "+f"((d)[3])              \
        : "r"((a)[0]), "r"((a)[1]), "r"((a)[2]), "r"((a)[3]),                 \
          "r"((b)[0]), "r"((b)[1]))

__device__ __forceinline__ uint32_t pack2(float x, float y) {
    __half2 h = __floats2half2_rn(x, y);
    return *(uint32_t*)&h;
}

// ---------------- 0a) pre-convert Ua_w -> fp16 granule layout ----------------
__global__ void k_convB(const float* __restrict__ Ua_w) {
    int gid = blockIdx.x * 256 + threadIdx.x;   // granule id, 32768 total
    int c = gid & 3;
    int t = gid >> 2;
    int row = t & 127;
    int kt = (t >> 7) & 15;
    int z = t >> 11;
    const float* src = Ua_w + ((size_t)(z * 128 + row) * HH + kt * 32 + c * 8);
    __half* dst = g_Ub16 + ((size_t)gid * 8);
    #pragma unroll
    for (int j = 0; j < 8; j++) dst[j] = __float2half_rn(src[j]);
}

// ---------------- 0b) pre-convert live keys tiles -> fp16 (coalesced) --------
__global__ __launch_bounds__(256) void k_convK(const float* __restrict__ keys,
                                               const int* __restrict__ valid) {
    int chunk = blockIdx.x, b = blockIdx.y;
    if (chunk * 128 >= valid[b]) return;
    size_t base = ((size_t)b * LK + chunk * 128) * HH;   // 65536 floats per tile
    const float* src = keys + base;
    __half* dst = g_keys16 + base;
    int tid = threadIdx.x;
    #pragma unroll
    for (int it = 0; it < 32; it++) {
        int off = (it * 256 + tid) * 8;      // 8 consecutive floats per thread
        float4 v0 = *(const float4*)(src + off);
        float4 v1 = *(const float4*)(src + off + 4);
        uint4 o = make_uint4(pack2(v0.x, v0.y), pack2(v0.z, v0.w),
                             pack2(v1.x, v1.y), pack2(v1.z, v1.w));
        *(uint4*)(dst + off) = o;
    }
}

// ---------------- 1) q projection (+ bias folding) --------------------------
__global__ void k_qc(const float* __restrict__ query, const float* __restrict__ Wa_w,
                     const float* __restrict__ Wa_b, const float* __restrict__ Ua_b) {
    __shared__ float qs[HH];
    int b = blockIdx.x, h = threadIdx.x;
    qs[h] = query[b * HH + h];
    __syncthreads();
    float acc = 0.f;
    const float* wr = Wa_w + (size_t)h * HH;
    #pragma unroll 8
    for (int j = 0; j < HH; j++) acc += qs[j] * wr[j];
    g_qc[b * HH + h] = acc + Wa_b[h] + Ua_b[h];
}

// ---------------- 2) fp16 mma GEMM, all-cp.async mainloop --------------------
// CTA: 128 l x 128 n. bx: lt=bx>>2, z=bx&3 (z fastest -> A shared via L2).
#define STG 10240                  // bytes per stage (128 rows * 80)
#define AOFF (4 * STG)             // A stages at 40960 + s*STG
#define QCOFF 81920
#define VAOFF 82432
#define REDOFF 82944
#define SMEM_SCORE 84992
__global__ __launch_bounds__(256, 2) void k_score_mma(
    const float* __restrict__ Va_w, const int* __restrict__ valid) {
    extern __shared__ char smem[];
    int lt = blockIdx.x >> 2, z = blockIdx.x & 3;
    int b = blockIdx.y;
    int l0 = lt * 128;
    int v = valid[b];
    if (l0 >= v) return;

    int tid = threadIdx.x;
    int wid = tid >> 5, lane = tid & 31;
    int mw = wid & 3, nw = wid >> 2;       // warp grid 4(M) x 2(N)
    int g = lane >> 2, tig = lane & 3;
    int n0 = z * 128;
    uint32_t sb = smem_u32(smem);

    float* qc_s = (float*)(smem + QCOFF);
    float* va_s = (float*)(smem + VAOFF);
    float* red  = (float*)(smem + REDOFF);
    if (tid < 128) {
        qc_s[tid] = g_qc[b * HH + n0 + tid];
        va_s[tid] = Va_w[n0 + tid];
    }
    __syncthreads();

    // ---- producer addressing (pure cp.async) ----
    int prow = tid >> 1, pseg = tid & 1;   // 2 threads per row, 32B each
    const __half* gA = g_keys16 + ((size_t)b * LK + l0 + prow) * HH + pseg * 16;
    uint32_t aDst0 = sb + AOFF + prow * 80 + pseg * 32;
    const __half* gB = g_Ub16 + (size_t)z * (16 * 128 * 32)
                     + ((size_t)prow * 4 + pseg * 2) * 8;
    uint32_t bDst0 = sb + prow * 80 + pseg * 32;

    // ---- ldmatrix addressing ----
    uint32_t aRow[2], bRow[4];
    #pragma unroll
    for (int mi = 0; mi < 2; mi++)
        aRow[mi] = (uint32_t)((mw * 32 + mi * 16 + ((lane >> 3) & 1) * 8 + (lane & 7)) * 80);
    #pragma unroll
    for (int nb4 = 0; nb4 < 4; nb4++)
        bRow[nb4] = (uint32_t)((nw * 64 + (nb4 * 2 + (lane >> 4)) * 8 + (lane & 7)) * 80);
    uint32_t cAh = (uint32_t)(lane >> 4) << 4;
    uint32_t cBh = (uint32_t)((lane >> 3) & 1) << 4;

    float d[2][8][4];
    #pragma unroll
    for (int mi = 0; mi < 2; mi++)
        #pragma unroll
        for (int ni = 0; ni < 8; ni++)
            #pragma unroll
            for (int jj = 0; jj < 4; jj++) d[mi][ni][jj] = 0.f;

    // ---- prologue: stages 0..2 for A and B ----
    #pragma unroll
    for (int s = 0; s < 3; s++) {
        const __half* sa = gA + s * 32;
        cpa16(aDst0 + s * STG, sa);
        cpa16(aDst0 + s * STG + 16, sa + 8);
        const __half* sbp = gB + (size_t)s * (128 * 32);
        cpa16(bDst0 + s * STG, sbp);
        cpa16(bDst0 + s * STG + 16, sbp + 8);
        CP_COMMIT();
    }

    for (int kt = 0; kt < 16; kt++) {
        CP_WAIT2();
        __syncthreads();
        if (kt + 3 < 16) {
            int s = kt + 3;
            const __half* sa = gA + s * 32;
            uint32_t ad = aDst0 + (s & 3) * STG;
            cpa16(ad, sa);
            cpa16(ad + 16, sa + 8);
            const __half* sbp = gB + (size_t)s * (128 * 32);
            uint32_t bd = bDst0 + (s & 3) * STG;
            cpa16(bd, sbp);
            cpa16(bd + 16, sbp + 8);
        }
        CP_COMMIT();

        uint32_t aBase = sb + AOFF + (kt & 3) * STG;
        uint32_t bBase = sb + (kt & 3) * STG;
        #pragma unroll
        for (int kg = 0; kg < 2; kg++) {
            uint32_t cA = ((uint32_t)(kg * 2) << 4) + cAh;
            uint32_t cB = ((uint32_t)(kg * 2) << 4) + cBh;
            uint32_t a[2][4], bf[8][2];
            #pragma unroll
            for (int mi = 0; mi < 2; mi++)
                LDSM_X4(a[mi][0], a[mi][1], a[mi][2], a[mi][3],
                        aBase + aRow[mi] + cA);
            // split B: first pair of LDSM feeds 8 MMAs while second pair loads
            LDSM_X4(bf[0][0], bf[0][1], bf[1][0], bf[1][1], bBase + bRow[0] + cB);
            LDSM_X4(bf[2][0], bf[2][1], bf[3][0], bf[3][1], bBase + bRow[1] + cB);
            #pragma unroll
            for (int mi = 0; mi < 2; mi++)
                #pragma unroll
                for (int ni = 0; ni < 4; ni++)
                    MMA_F16(d[mi][ni], a[mi], bf[ni]);
            LDSM_X4(bf[4][0], bf[4][1], bf[5][0], bf[5][1], bBase + bRow[2] + cB);
            LDSM_X4(bf[6][0], bf[6][1], bf[7][0], bf[7][1], bBase + bRow[3] + cB);
            #pragma unroll
            for (int mi = 0; mi < 2; mi++)
                #pragma unroll
                for (int ni = 4; ni < 8; ni++)
                    MMA_F16(d[mi][ni], a[mi], bf[ni]);
        }
    }

    // ---- epilogue: tanh + Va dot, reduce across n ---------------------------
    float rs[2][2] = {{0.f, 0.f}, {0.f, 0.f}};
    #pragma unroll
    for (int mi = 0; mi < 2; mi++)
        #pragma unroll
        for (int ni = 0; ni < 8; ni++)
            #pragma unroll
            for (int jj = 0; jj < 4; jj++) {
                int nl = nw * 64 + ni * 8 + tig * 2 + (jj & 1);
                rs[mi][jj >> 1] += fast_tanh(d[mi][ni][jj] + qc_s[nl]) * va_s[nl];
            }
    #pragma unroll
    for (int mi = 0; mi < 2; mi++)
        #pragma unroll
        for (int hh = 0; hh < 2; hh++) {
            float s = rs[mi][hh];
            s += __shfl_xor_sync(0xffffffffu, s, 1);
            s += __shfl_xor_sync(0xffffffffu, s, 2);
            rs[mi][hh] = s;
        }
    if (tig == 0) {
        #pragma unroll
        for (int mi = 0; mi < 2; mi++)
            #pragma unroll
            for (int hh = 0; hh < 2; hh++) {
                int row = mw * 32 + mi * 16 + hh * 8 + g;
                red[row * 2 + nw] = rs[mi][hh];
            }
    }
    __syncthreads();
    if (tid < 128)
        g_spart[((size_t)z * BB + b) * LK + l0 + tid] = red[tid * 2] + red[tid * 2 + 1];
}

// ---------------- 3) softmax over Lk per batch (sums 4 partials) -------------
__global__ void k_softmax(const float* __restrict__ Va_b, const float* __restrict__ temp,
                          const int* __restrict__ valid, float* __restrict__ w_out) {
    __shared__ float se[LK];
    __shared__ float rbuf[1024];
    int b = blockIdx.x, tid = threadIdx.x;
    int v = valid[b];
    float vb = Va_b[0], invT = 1.f / temp[0];
    const float* p0 = g_spart + ((size_t)0 * BB + b) * LK;
    const float* p1 = g_spart + ((size_t)1 * BB + b) * LK;
    const float* p2 = g_spart + ((size_t)2 * BB + b) * LK;
    const float* p3 = g_spart + ((size_t)3 * BB + b) * LK;
    float mx = -1e30f;
    for (int l = tid; l < LK; l += 1024) {
        float s = (l < v) ? (p0[l] + p1[l] + p2[l] + p3[l] + vb) * invT : -1e9f;
        se[l] = s; mx = fmaxf(mx, s);
    }
    rbuf[tid] = mx; __syncthreads();
    for (int s = 512; s > 0; s >>= 1) {
        if (tid < s) rbuf[tid] = fmaxf(rbuf[tid], rbuf[tid + s]);
        __syncthreads();
    }
    mx = rbuf[0]; __syncthreads();
    float sum = 0.f;
    for (int l = tid; l < LK; l += 1024) { float e = expf(se[l] - mx); se[l] = e; sum += e; }
    rbuf[tid] = sum; __syncthreads();
    for (int s = 512; s > 0; s >>= 1) {
        if (tid < s) rbuf[tid] += rbuf[tid + s];
        __syncthreads();
    }
    float inv = 1.f / rbuf[0];
    for (int l = tid; l < LK; l += 1024) w_out[(size_t)b * LK + l] = se[l] * inv;
}

// ---------------- 4) context partials (half2-vectorized, coalesced) ----------
__global__ __launch_bounds__(256) void k_ctx(const float* __restrict__ w,
                                             const int* __restrict__ valid) {
    __shared__ float ws[128];
    int b = blockIdx.y;
    int chunk = blockIdx.x;
    int lbase = chunk * 128;
    int tid = threadIdx.x;               // 0..255 -> h pair (2*tid, 2*tid+1)
    int v = valid[b];
    float ax0 = 0.f, ay0 = 0.f, ax1 = 0.f, ay1 = 0.f;
    if (lbase < v) {
        int lend = min(128, v - lbase);
        if (tid < 128) ws[tid] = w[(size_t)b * LK + lbase + tid];
        __syncthreads();
        const __half2* kb =
            (const __half2*)(g_keys16 + ((size_t)b * LK + lbase) * HH) + tid;
        const int str = HH / 2;          // half2 stride per row
        int l = 0;
        for (; l + 2 <= lend; l += 2) {
            float2 k0 = __half22float2(kb[(size_t)l * str]);
            float2 k1 = __half22float2(kb[(size_t)(l + 1) * str]);
            float w0 = ws[l], w1 = ws[l + 1];
            ax0 += w0 * k0.x; ay0 += w0 * k0.y;
            ax1 += w1 * k1.x; ay1 += w1 * k1.y;
        }
        if (l < lend) {
            float2 k0 = __half22float2(kb[(size_t)l * str]);
            float w0 = ws[l];
            ax0 += w0 * k0.x; ay0 += w0 * k0.y;
        }
    }
    float* dst = g_part + ((size_t)chunk * BB + b) * HH;
    dst[tid * 2]     = ax0 + ax1;
    dst[tid * 2 + 1] = ay0 + ay1;
}

// ---------------- 5) reduce partials -> context ------------------------------
__global__ void k_ctxred(float* __restrict__ ctx_out) {
    int b = blockIdx.x, h = threadIdx.x;
    float s = 0.f;
    #pragma unroll
    for (int c = 0; c < 32; c++) s += g_part[((size_t)c * BB + b) * HH + h];
    ctx_out[b * HH + h] = s;
}

// ---------------- launch ------------------------------------------------------
extern "C" void kernel_launch(void* const* d_in, const int* in_sizes, int n_in,
                              void* d_out, int out_size) {
    const float* query = (const float*)d_in[0];
    const float* keys  = (const float*)d_in[1];
    const float* Wa_w  = (const float*)d_in[2];
    const float* Wa_b  = (const float*)d_in[3];
    const float* Ua_w  = (const float*)d_in[4];
    const float* Ua_b  = (const float*)d_in[5];
    const float* Va_w  = (const float*)d_in[6];
    const float* Va_b  = (const float*)d_in[7];
    const float* temp  = (const float*)d_in[8];
    const int*   valid = (const int*)d_in[9];

    float* out = (float*)d_out;
    float* ctx_out;
    float* w_out;
    void *cb = nullptr, *wb = nullptr;
    cudaGetSymbolAddress(&cb, g_cbuf);
    cudaGetSymbolAddress(&wb, g_wbuf);
    if (out_size >= BB * HH + BB * LK) { ctx_out = out; w_out = out + BB * HH; }
    else if (out_size == BB * LK)      { w_out = out; ctx_out = (float*)cb; }
    else                               { ctx_out = out; w_out = (float*)wb; }

    cudaFuncSetAttribute(k_score_mma, cudaFuncAttributeMaxDynamicSharedMemorySize,
                         SMEM_SCORE);

    k_convB<<<128, 256>>>(Ua_w);
    k_convK<<<dim3(LK / 128, BB), 256>>>(keys, valid);
    k_qc<<<BB, HH>>>(query, Wa_w, Wa_b, Ua_b);
    k_score_mma<<<dim3(4 * (LK / 128), BB), 256, SMEM_SCORE>>>(Va_w, valid);
    k_softmax<<<BB, 1024>>>(Va_b, temp, valid, w_out);
    k_ctx<<<dim3(LK / 128, BB), 256>>>(w_out, valid);
    k_ctxred<<<BB, HH>>>(ctx_out);
}

// round 16
// speedup vs baseline: 1.5682x; 1.0861x over previous
#include <cuda_runtime.h>
#include <cuda_fp16.h>
#include <cstdint>
#include <math.h>

#define BB 32
#define LK 4096
#define HH 512

// ---------------- scratch (device globals; no allocations allowed) ----------
__device__ float g_qc[BB * HH];           // Wa q + Wa_b + Ua_b
__device__ float g_spart[4 * BB * LK];    // per-nchunk partial scores
__device__ float g_part[32 * BB * HH];    // context partials per 128-l chunk
__device__ float g_wbuf[BB * LK];         // fallback weights output
__device__ float g_cbuf[BB * HH];         // fallback context output
__device__ __half g_Ub16[4 * 16 * 128 * 32];   // Ua_w fp16 granules [z][kt][row][c][8]
__device__ __half g_keys16[(size_t)BB * LK * HH];  // keys fp16 (live tiles only)

// ================= helpers ===================================================
__device__ __forceinline__ uint32_t smem_u32(const void* p) {
    uint32_t a;
    asm("{ .reg .u64 t; cvta.to.shared.u64 t, %1; cvt.u32.u64 %0, t; }"
        : "=r"(a) : "l"(p));
    return a;
}
// HW tanh (sm_75+): single MUFU op, max rel err ~2^-11
__device__ __forceinline__ float hw_tanh(float x) {
    float r; asm("tanh.approx.f32 %0, %1;" : "=f"(r) : "f"(x));
    return r;
}
__device__ __forceinline__ void cpa16(uint32_t saddr, const void* g) {
    asm volatile("cp.async.cg.shared.global [%0], [%1], 16;" :: "r"(saddr), "l"(g));
}
#define CP_COMMIT() asm volatile("cp.async.commit_group;" ::: "memory")
#define CP_WAIT2()  asm volatile("cp.async.wait_group 2;" ::: "memory")

#define LDSM_X4(r0, r1, r2, r3, addr)                                         \
    asm volatile("ldmatrix.sync.aligned.m8n8.x4.shared.b16 {%0,%1,%2,%3}, [%4];" \
        : "=r"(r0), "=r"(r1), "=r"(r2), "=r"(r3) : "r"(addr))

#define MMA_F16(d, a, b)                                                      \
    asm volatile(                                                             \
        "mma.sync.aligned.m16n8k16.row.col.f32.f16.f16.f32 "                  \
        "{%0,%1,%2,%3}, {%4,%5,%6,%7}, {%8,%9}, {%0,%1,%2,%3};"               \
        : "+f"((d)[0]), "+f"((d)[1]), "+f"((d)[2]), "+f"((d)[3])              \
        : "r"((a)[0]), "r"((a)[1]), "r"((a)[2]), "r"((a)[3]),                 \
          "r"((b)[0]), "r"((b)[1]))

__device__ __forceinline__ uint32_t pack2(float x, float y) {
    __half2 h = __floats2half2_rn(x, y);
    return *(uint32_t*)&h;
}

// ---------------- 0a) pre-convert Ua_w -> fp16 granule layout ----------------
__global__ void k_convB(const float* __restrict__ Ua_w) {
    int gid = blockIdx.x * 256 + threadIdx.x;   // granule id, 32768 total
    int c = gid & 3;
    int t = gid >> 2;
    int row = t & 127;
    int kt = (t >> 7) & 15;
    int z = t >> 11;
    const float* src = Ua_w + ((size_t)(z * 128 + row) * HH + kt * 32 + c * 8);
    __half* dst = g_Ub16 + ((size_t)gid * 8);
    #pragma unroll
    for (int j = 0; j < 8; j++) dst[j] = __float2half_rn(src[j]);
}

// ---------------- 0b) pre-convert live keys tiles -> fp16 (coalesced) --------
__global__ __launch_bounds__(256) void k_convK(const float* __restrict__ keys,
                                               const int* __restrict__ valid) {
    int chunk = blockIdx.x, b = blockIdx.y;
    if (chunk * 128 >= valid[b]) return;
    size_t base = ((size_t)b * LK + chunk * 128) * HH;   // 65536 floats per tile
    const float* src = keys + base;
    __half* dst = g_keys16 + base;
    int tid = threadIdx.x;
    #pragma unroll
    for (int it = 0; it < 32; it++) {
        int off = (it * 256 + tid) * 8;      // 8 consecutive floats per thread
        float4 v0 = *(const float4*)(src + off);
        float4 v1 = *(const float4*)(src + off + 4);
        uint4 o = make_uint4(pack2(v0.x, v0.y), pack2(v0.z, v0.w),
                             pack2(v1.x, v1.y), pack2(v1.z, v1.w));
        *(uint4*)(dst + off) = o;
    }
}

// ---------------- 1) q projection (+ bias folding) --------------------------
__global__ void k_qc(const float* __restrict__ query, const float* __restrict__ Wa_w,
                     const float* __restrict__ Wa_b, const float* __restrict__ Ua_b) {
    __shared__ float qs[HH];
    int b = blockIdx.x, h = threadIdx.x;
    qs[h] = query[b * HH + h];
    __syncthreads();
    float acc = 0.f;
    const float* wr = Wa_w + (size_t)h * HH;
    #pragma unroll 8
    for (int j = 0; j < HH; j++) acc += qs[j] * wr[j];
    g_qc[b * HH + h] = acc + Wa_b[h] + Ua_b[h];
}

// ---------------- 2) fp16 mma GEMM, all-cp.async mainloop (round-11 body) ----
#define STG 10240                  // bytes per stage (128 rows * 80)
#define AOFF (4 * STG)             // A stages at 40960 + s*STG
#define QCOFF 81920
#define VAOFF 82432
#define REDOFF 82944
#define SMEM_SCORE 84992
__global__ __launch_bounds__(256, 2) void k_score_mma(
    const float* __restrict__ Va_w, const int* __restrict__ valid) {
    extern __shared__ char smem[];
    int lt = blockIdx.x >> 2, z = blockIdx.x & 3;
    int b = blockIdx.y;
    int l0 = lt * 128;
    int v = valid[b];
    if (l0 >= v) return;

    int tid = threadIdx.x;
    int wid = tid >> 5, lane = tid & 31;
    int mw = wid & 3, nw = wid >> 2;       // warp grid 4(M) x 2(N)
    int g = lane >> 2, tig = lane & 3;
    int n0 = z * 128;
    uint32_t sb = smem_u32(smem);

    float* qc_s = (float*)(smem + QCOFF);
    float* va_s = (float*)(smem + VAOFF);
    float* red  = (float*)(smem + REDOFF);
    if (tid < 128) {
        qc_s[tid] = g_qc[b * HH + n0 + tid];
        va_s[tid] = Va_w[n0 + tid];
    }
    __syncthreads();

    // ---- producer addressing (pure cp.async) ----
    int prow = tid >> 1, pseg = tid & 1;   // 2 threads per row, 32B each
    const __half* gA = g_keys16 + ((size_t)b * LK + l0 + prow) * HH + pseg * 16;
    uint32_t aDst0 = sb + AOFF + prow * 80 + pseg * 32;
    const __half* gB = g_Ub16 + (size_t)z * (16 * 128 * 32)
                     + ((size_t)prow * 4 + pseg * 2) * 8;
    uint32_t bDst0 = sb + prow * 80 + pseg * 32;

    // ---- ldmatrix addressing ----
    uint32_t aRow[2], bRow[4];
    #pragma unroll
    for (int mi = 0; mi < 2; mi++)
        aRow[mi] = (uint32_t)((mw * 32 + mi * 16 + ((lane >> 3) & 1) * 8 + (lane & 7)) * 80);
    #pragma unroll
    for (int nb4 = 0; nb4 < 4; nb4++)
        bRow[nb4] = (uint32_t)((nw * 64 + (nb4 * 2 + (lane >> 4)) * 8 + (lane & 7)) * 80);
    uint32_t cAh = (uint32_t)(lane >> 4) << 4;
    uint32_t cBh = (uint32_t)((lane >> 3) & 1) << 4;

    float d[2][8][4];
    #pragma unroll
    for (int mi = 0; mi < 2; mi++)
        #pragma unroll
        for (int ni = 0; ni < 8; ni++)
            #pragma unroll
            for (int jj = 0; jj < 4; jj++) d[mi][ni][jj] = 0.f;

    // ---- prologue: stages 0..2 for A and B ----
    #pragma unroll
    for (int s = 0; s < 3; s++) {
        const __half* sa = gA + s * 32;
        cpa16(aDst0 + s * STG, sa);
        cpa16(aDst0 + s * STG + 16, sa + 8);
        const __half* sbp = gB + (size_t)s * (128 * 32);
        cpa16(bDst0 + s * STG, sbp);
        cpa16(bDst0 + s * STG + 16, sbp + 8);
        CP_COMMIT();
    }

    for (int kt = 0; kt < 16; kt++) {
        CP_WAIT2();
        __syncthreads();
        if (kt + 3 < 16) {
            int s = kt + 3;
            const __half* sa = gA + s * 32;
            uint32_t ad = aDst0 + (s & 3) * STG;
            cpa16(ad, sa);
            cpa16(ad + 16, sa + 8);
            const __half* sbp = gB + (size_t)s * (128 * 32);
            uint32_t bd = bDst0 + (s & 3) * STG;
            cpa16(bd, sbp);
            cpa16(bd + 16, sbp + 8);
        }
        CP_COMMIT();

        uint32_t aBase = sb + AOFF + (kt & 3) * STG;
        uint32_t bBase = sb + (kt & 3) * STG;
        #pragma unroll
        for (int kg = 0; kg < 2; kg++) {
            uint32_t cA = ((uint32_t)(kg * 2) << 4) + cAh;
            uint32_t cB = ((uint32_t)(kg * 2) << 4) + cBh;
            uint32_t a[2][4], bf[8][2];
            #pragma unroll
            for (int mi = 0; mi < 2; mi++)
                LDSM_X4(a[mi][0], a[mi][1], a[mi][2], a[mi][3],
                        aBase + aRow[mi] + cA);
            #pragma unroll
            for (int nb4 = 0; nb4 < 4; nb4++)
                LDSM_X4(bf[nb4 * 2][0], bf[nb4 * 2][1],
                        bf[nb4 * 2 + 1][0], bf[nb4 * 2 + 1][1],
                        bBase + bRow[nb4] + cB);
            #pragma unroll
            for (int mi = 0; mi < 2; mi++)
                #pragma unroll
                for (int ni = 0; ni < 8; ni++)
                    MMA_F16(d[mi][ni], a[mi], bf[ni]);
        }
    }

    // ---- epilogue: HW tanh + Va dot, reduce across n ------------------------
    float rs[2][2] = {{0.f, 0.f}, {0.f, 0.f}};
    #pragma unroll
    for (int mi = 0; mi < 2; mi++)
        #pragma unroll
        for (int ni = 0; ni < 8; ni++)
            #pragma unroll
            for (int jj = 0; jj < 4; jj++) {
                int nl = nw * 64 + ni * 8 + tig * 2 + (jj & 1);
                rs[mi][jj >> 1] += hw_tanh(d[mi][ni][jj] + qc_s[nl]) * va_s[nl];
            }
    #pragma unroll
    for (int mi = 0; mi < 2; mi++)
        #pragma unroll
        for (int hh = 0; hh < 2; hh++) {
            float s = rs[mi][hh];
            s += __shfl_xor_sync(0xffffffffu, s, 1);
            s += __shfl_xor_sync(0xffffffffu, s, 2);
            rs[mi][hh] = s;
        }
    if (tig == 0) {
        #pragma unroll
        for (int mi = 0; mi < 2; mi++)
            #pragma unroll
            for (int hh = 0; hh < 2; hh++) {
                int row = mw * 32 + mi * 16 + hh * 8 + g;
                red[row * 2 + nw] = rs[mi][hh];
            }
    }
    __syncthreads();
    if (tid < 128)
        g_spart[((size_t)z * BB + b) * LK + l0 + tid] = red[tid * 2] + red[tid * 2 + 1];
}

// ---------------- 3) softmax over Lk per batch (sums 4 partials) -------------
__global__ void k_softmax(const float* __restrict__ Va_b, const float* __restrict__ temp,
                          const int* __restrict__ valid, float* __restrict__ w_out) {
    __shared__ float se[LK];
    __shared__ float rbuf[1024];
    int b = blockIdx.x, tid = threadIdx.x;
    int v = valid[b];
    float vb = Va_b[0], invT = 1.f / temp[0];
    const float* p0 = g_spart + ((size_t)0 * BB + b) * LK;
    const float* p1 = g_spart + ((size_t)1 * BB + b) * LK;
    const float* p2 = g_spart + ((size_t)2 * BB + b) * LK;
    const float* p3 = g_spart + ((size_t)3 * BB + b) * LK;
    float mx = -1e30f;
    for (int l = tid; l < LK; l += 1024) {
        float s = (l < v) ? (p0[l] + p1[l] + p2[l] + p3[l] + vb) * invT : -1e9f;
        se[l] = s; mx = fmaxf(mx, s);
    }
    rbuf[tid] = mx; __syncthreads();
    for (int s = 512; s > 0; s >>= 1) {
        if (tid < s) rbuf[tid] = fmaxf(rbuf[tid], rbuf[tid + s]);
        __syncthreads();
    }
    mx = rbuf[0]; __syncthreads();
    float sum = 0.f;
    for (int l = tid; l < LK; l += 1024) { float e = expf(se[l] - mx); se[l] = e; sum += e; }
    rbuf[tid] = sum; __syncthreads();
    for (int s = 512; s > 0; s >>= 1) {
        if (tid < s) rbuf[tid] += rbuf[tid + s];
        __syncthreads();
    }
    float inv = 1.f / rbuf[0];
    for (int l = tid; l < LK; l += 1024) w_out[(size_t)b * LK + l] = se[l] * inv;
}

// ---------------- 4) context partials (half2-vectorized, coalesced) ----------
__global__ __launch_bounds__(256) void k_ctx(const float* __restrict__ w,
                                             const int* __restrict__ valid) {
    __shared__ float ws[128];
    int b = blockIdx.y;
    int chunk = blockIdx.x;
    int lbase = chunk * 128;
    int tid = threadIdx.x;               // 0..255 -> h pair (2*tid, 2*tid+1)
    int v = valid[b];
    float ax0 = 0.f, ay0 = 0.f, ax1 = 0.f, ay1 = 0.f;
    if (lbase < v) {
        int lend = min(128, v - lbase);
        if (tid < 128) ws[tid] = w[(size_t)b * LK + lbase + tid];
        __syncthreads();
        const __half2* kb =
            (const __half2*)(g_keys16 + ((size_t)b * LK + lbase) * HH) + tid;
        const int str = HH / 2;          // half2 stride per row
        int l = 0;
        for (; l + 2 <= lend; l += 2) {
            float2 k0 = __half22float2(kb[(size_t)l * str]);
            float2 k1 = __half22float2(kb[(size_t)(l + 1) * str]);
            float w0 = ws[l], w1 = ws[l + 1];
            ax0 += w0 * k0.x; ay0 += w0 * k0.y;
            ax1 += w1 * k1.x; ay1 += w1 * k1.y;
        }
        if (l < lend) {
            float2 k0 = __half22float2(kb[(size_t)l * str]);
            float w0 = ws[l];
            ax0 += w0 * k0.x; ay0 += w0 * k0.y;
        }
    }
    float* dst = g_part + ((size_t)chunk * BB + b) * HH;
    dst[tid * 2]     = ax0 + ax1;
    dst[tid * 2 + 1] = ay0 + ay1;
}

// ---------------- 5) reduce partials -> context ------------------------------
__global__ void k_ctxred(float* __restrict__ ctx_out) {
    int b = blockIdx.x, h = threadIdx.x;
    float s = 0.f;
    #pragma unroll
    for (int c = 0; c < 32; c++) s += g_part[((size_t)c * BB + b) * HH + h];
    ctx_out[b * HH + h] = s;
}

// ---------------- launch ------------------------------------------------------
extern "C" void kernel_launch(void* const* d_in, const int* in_sizes, int n_in,
                              void* d_out, int out_size) {
    const float* query = (const float*)d_in[0];
    const float* keys  = (const float*)d_in[1];
    const float* Wa_w  = (const float*)d_in[2];
    const float* Wa_b  = (const float*)d_in[3];
    const float* Ua_w  = (const float*)d_in[4];
    const float* Ua_b  = (const float*)d_in[5];
    const float* Va_w  = (const float*)d_in[6];
    const float* Va_b  = (const float*)d_in[7];
    const float* temp  = (const float*)d_in[8];
    const int*   valid = (const int*)d_in[9];

    float* out = (float*)d_out;
    float* ctx_out;
    float* w_out;
    void *cb = nullptr, *wb = nullptr;
    cudaGetSymbolAddress(&cb, g_cbuf);
    cudaGetSymbolAddress(&wb, g_wbuf);
    if (out_size >= BB * HH + BB * LK) { ctx_out = out; w_out = out + BB * HH; }
    else if (out_size == BB * LK)      { w_out = out; ctx_out = (float*)cb; }
    else                               { ctx_out = out; w_out = (float*)wb; }

    cudaFuncSetAttribute(k_score_mma, cudaFuncAttributeMaxDynamicSharedMemorySize,
                         SMEM_SCORE);

    k_convB<<<128, 256>>>(Ua_w);
    k_convK<<<dim3(LK / 128, BB), 256>>>(keys, valid);
    k_qc<<<BB, HH>>>(query, Wa_w, Wa_b, Ua_b);
    k_score_mma<<<dim3(4 * (LK / 128), BB), 256, SMEM_SCORE>>>(Va_w, valid);
    k_softmax<<<BB, 1024>>>(Va_b, temp, valid, w_out);
    k_ctx<<<dim3(LK / 128, BB), 256>>>(w_out, valid);
    k_ctxred<<<BB, HH>>>(ctx_out);
}